// round 6
// baseline (speedup 1.0000x reference)
#include <cuda_runtime.h>
#include <cstdint>
#include <math.h>
#include <math_constants.h>

#define BN 8192
#define DIM 256
#define NB 1024
#define NTILE 2080                 // upper-triangle 64x64 tiles
#define TILE_ELEMS 16384           // 128*128
#define SROWB 144                  // padded smem row bytes (36 floats)
#define SLABB (128 * SROWB)        // 18432
#define STAGEB (2 * SLABB)         // 36864
#define SMEM_TOTAL (2 * STAGEB + 1024)

static __device__ float  g_Dscr[2ull * NTILE * TILE_ELEMS];   // 272 MB scratch
static __device__ float  g_xx_a[BN];
static __device__ float  g_xx_b[BN];
static __device__ double g_rowsum_a[BN];
static __device__ double g_rowsum_b[BN];
static __device__ double g_grand[2];
static __device__ double g_prod[3];
static __device__ double g_Sexp[2 * NB];
static __device__ double g_Sevexp[2 * NB];
static __device__ double g_Sevr[2 * NB];
static __device__ int    g_dcnt[2 * NB];
static __device__ float  g_maxr[2];
static __device__ double g_cox[2];

// ----------------------------- helpers ---------------------------------------
__device__ __forceinline__ uint32_t smem_u32(const void* p) {
    uint32_t a;
    asm("{ .reg .u64 t; cvta.to.shared.u64 t, %1; cvt.u32.u64 %0, t; }" : "=r"(a) : "l"(p));
    return a;
}
#define CP16(d, s) asm volatile("cp.async.cg.shared.global [%0], [%1], 16;" :: "r"(d), "l"(s))
#define CP_COMMIT() asm volatile("cp.async.commit_group;" ::: "memory")
#define CP_WAIT(n)  asm volatile("cp.async.wait_group %0;" :: "n"(n) : "memory")

__device__ __forceinline__ void fma2(unsigned long long& acc, unsigned long long a,
                                     unsigned long long b) {
    asm("fma.rn.f32x2 %0, %1, %2, %0;" : "+l"(acc) : "l"(a), "l"(b));
}
__device__ __forceinline__ float acc_sum(unsigned long long u) {
    float lo = __uint_as_float((uint32_t)u);
    float hi = __uint_as_float((uint32_t)(u >> 32));
    return lo + hi;
}

// ------------------------------- small kernels -------------------------------
__global__ void k_zero() {
    int t = blockIdx.x * blockDim.x + threadIdx.x;
    if (t < BN) { g_rowsum_a[t] = 0.0; g_rowsum_b[t] = 0.0; }
    if (t < 2 * NB) { g_Sexp[t] = 0.0; g_Sevexp[t] = 0.0; g_Sevr[t] = 0.0; g_dcnt[t] = 0; }
    if (t == 0) {
        g_grand[0] = g_grand[1] = 0.0;
        g_prod[0] = g_prod[1] = g_prod[2] = 0.0;
    }
}

__global__ void k_max(const float* __restrict__ r0, const float* __restrict__ r1) {
    const float* r = blockIdx.x ? r1 : r0;
    __shared__ float s[256];
    float m = -CUDART_INF_F;
    for (int i = threadIdx.x; i < BN; i += 256) m = fmaxf(m, r[i]);
    s[threadIdx.x] = m;
    __syncthreads();
    for (int o = 128; o > 0; o >>= 1) {
        if (threadIdx.x < o) s[threadIdx.x] = fmaxf(s[threadIdx.x], s[threadIdx.x + o]);
        __syncthreads();
    }
    if (threadIdx.x == 0) g_maxr[blockIdx.x] = s[0];
}

__global__ void k_bucket(const float* __restrict__ r0, const int* __restrict__ e0,
                         const int* __restrict__ t0,
                         const float* __restrict__ r1, const int* __restrict__ e1,
                         const int* __restrict__ t1) {
    int task = blockIdx.y;
    int i = blockIdx.x * 256 + threadIdx.x;
    if (i >= BN) return;
    const float* r = task ? r1 : r0;
    const int* ev = task ? e1 : e0;
    const int* tm = task ? t1 : t0;
    float rs = r[i] - g_maxr[task];
    double er = exp((double)rs);
    int t = tm[i];
    t = t < 0 ? 0 : (t > NB - 1 ? NB - 1 : t);
    int base = task * NB;
    atomicAdd(&g_Sexp[base + t], er);
    if (ev[i]) {
        atomicAdd(&g_Sevexp[base + t], er);
        atomicAdd(&g_Sevr[base + t], (double)rs);
        atomicAdd(&g_dcnt[base + t], 1);
    }
}

__global__ void k_cox() {
    int task = threadIdx.x;
    if (task >= 2) return;
    int base = task * NB;
    double cum = 0.0, num = 0.0, nev = 0.0;
    for (int t = NB - 1; t >= 0; --t) {
        cum += g_Sexp[base + t];
        int d = g_dcnt[base + t];
        if (d > 0) {
            double tes = g_Sevexp[base + t];
            num += g_Sevr[base + t];
            double dd = (double)d;
            for (int l = 0; l < d; ++l)
                num -= log(cum - ((double)l / dd) * tes + 1e-12);
            nev += dd;
        }
    }
    g_cox[task] = -num / (nev + 1e-12);
}

__global__ void k_xx(const float* __restrict__ za, const float* __restrict__ zb) {
    int row = blockIdx.x * 8 + (threadIdx.x >> 5);
    int lane = threadIdx.x & 31;
    if (row >= BN) return;
    const float* pa = za + (size_t)row * DIM;
    const float* pb = zb + (size_t)row * DIM;
    float sa = 0.f, sb = 0.f;
    for (int k = lane; k < DIM; k += 32) {
        float va = pa[k]; sa += va * va;
        float vb = pb[k]; sb += vb * vb;
    }
    for (int o = 16; o; o >>= 1) {
        sa += __shfl_down_sync(0xffffffffu, sa, o);
        sb += __shfl_down_sync(0xffffffffu, sb, o);
    }
    if (lane == 0) { g_xx_a[row] = sa; g_xx_b[row] = sb; }
}

// ---------------- pass 1: f32x2 SIMT gram -> distances + row sums ------------
__global__ void __launch_bounds__(256, 1) k_gram(const float* __restrict__ za,
                                                 const float* __restrict__ zb) {
    int bi = blockIdx.y, bj = blockIdx.x;
    if (bj < bi) return;
    int g = blockIdx.z;
    const float* z = g ? zb : za;
    const float* xx = g ? g_xx_b : g_xx_a;
    double* rs = g ? g_rowsum_b : g_rowsum_a;
    int i0 = bi * 128, j0 = bj * 128;
    bool diag = (bi == bj);
    size_t L = (size_t)bi * 64 - (size_t)bi * (bi - 1) / 2 + (size_t)(bj - bi);
    float* dst = g_Dscr + (size_t)g * ((size_t)NTILE * TILE_ELEMS) + L * TILE_ELEMS;

    extern __shared__ char smem[];
    uint32_t sbase = smem_u32(smem);
    float* sxr = (float*)(smem + 2 * STAGEB);
    float* sxc = (float*)(smem + 2 * STAGEB + 512);

    int tid = threadIdx.x;
    int tx = tid & 15, ty = tid >> 4, lane = tid & 31;
    if (tid < 128) { sxr[tid] = xx[i0 + tid]; sxc[tid] = xx[j0 + tid]; }

    int crow = tid >> 1, ch = tid & 1;
    const char* srcRbase = (const char*)z + ((size_t)(i0 + crow)) * 1024 + ch * 64;
    const char* srcCbase = (const char*)z + ((size_t)(j0 + crow)) * 1024 + ch * 64;
    uint32_t dR = crow * SROWB + ch * 64;
    uint32_t dC = SLABB + crow * SROWB + ch * 64;

    unsigned long long acc[8][8];
#pragma unroll
    for (int m = 0; m < 8; ++m)
#pragma unroll
        for (int n = 0; n < 8; ++n) acc[m][n] = 0ull;

    // prefetch chunk 0
    {
        uint32_t stg = sbase;
#pragma unroll
        for (int i = 0; i < 4; ++i) {
            CP16(stg + dR + i * 16, srcRbase + i * 16);
            CP16(stg + dC + i * 16, srcCbase + i * 16);
        }
        CP_COMMIT();
    }

    for (int c = 0; c < 8; ++c) {
        if (c < 7) {
            uint32_t stg = sbase + ((c + 1) & 1) * STAGEB;
            size_t ko = (size_t)(c + 1) * 128;
#pragma unroll
            for (int i = 0; i < 4; ++i) {
                CP16(stg + dR + i * 16, srcRbase + ko + i * 16);
                CP16(stg + dC + i * 16, srcCbase + ko + i * 16);
            }
            CP_COMMIT();
            CP_WAIT(1);
        } else {
            CP_WAIT(0);
        }
        __syncthreads();

        const char* rowslab = smem + (c & 1) * STAGEB;
        const char* colslab = rowslab + SLABB;
#pragma unroll
        for (int k4 = 0; k4 < 8; ++k4) {
            ulonglong2 A[8];
#pragma unroll
            for (int m = 0; m < 8; ++m)
                A[m] = *(const ulonglong2*)(rowslab + (ty + 16 * m) * SROWB + k4 * 16);
#pragma unroll
            for (int n = 0; n < 8; ++n) {
                ulonglong2 B = *(const ulonglong2*)(colslab + (tx + 16 * n) * SROWB + k4 * 16);
#pragma unroll
                for (int m = 0; m < 8; ++m) {
                    fma2(acc[m][n], A[m].x, B.x);
                    fma2(acc[m][n], A[m].y, B.y);
                }
            }
        }
        __syncthreads();
    }

    // ---------------- epilogue ----------------
    float xr[8], xc[8];
#pragma unroll
    for (int m = 0; m < 8; ++m) xr[m] = sxr[ty + 16 * m];
#pragma unroll
    for (int n = 0; n < 8; ++n) xc[n] = sxc[tx + 16 * n];

    float csum[8] = {0, 0, 0, 0, 0, 0, 0, 0};
#pragma unroll
    for (int m = 0; m < 8; ++m) {
        float d8[8];
        float rsum = 0.f;
#pragma unroll
        for (int n = 0; n < 8; ++n) {
            float gg = acc_sum(acc[m][n]);
            float D = sqrtf(fmaxf(xr[m] + xc[n] - 2.f * gg, 1e-8f));
            d8[n] = D;
            rsum += D;
            csum[n] += D;
        }
#pragma unroll
        for (int q = 0; q < 2; ++q) {
            float4 w4 = make_float4(d8[4 * q], d8[4 * q + 1], d8[4 * q + 2], d8[4 * q + 3]);
            *(float4*)(dst + (size_t)(m * 2 + q) * 1024 + tid * 4) = w4;
        }
        rsum += __shfl_xor_sync(0xffffffffu, rsum, 1);
        rsum += __shfl_xor_sync(0xffffffffu, rsum, 2);
        rsum += __shfl_xor_sync(0xffffffffu, rsum, 4);
        rsum += __shfl_xor_sync(0xffffffffu, rsum, 8);
        if ((lane & 15) == 0)
            atomicAdd(&rs[i0 + ty + 16 * m], (double)rsum);
    }

    if (!diag) {   // mirror column sums
        float* scol = (float*)smem;   // stage0 reuse (no more frag reads)
        if (tid < 128) scol[tid] = 0.f;
        __syncthreads();
#pragma unroll
        for (int n = 0; n < 8; ++n) atomicAdd(&scol[tx + 16 * n], csum[n]);
        __syncthreads();
        if (tid < 128) atomicAdd(&rs[j0 + tid], (double)scol[tid]);
    }
}

// ---------------- pass 2: streaming products over scratch --------------------
__global__ void __launch_bounds__(256) k_prod() {
    int bi = blockIdx.y, bj = blockIdx.x;
    if (bj < bi) return;
    size_t L = (size_t)bi * 64 - (size_t)bi * (bi - 1) / 2 + (size_t)(bj - bi);
    const float4* A = (const float4*)(g_Dscr + L * TILE_ELEMS);
    const float4* B = (const float4*)(g_Dscr + (size_t)NTILE * TILE_ELEMS + L * TILE_ELEMS);
    float ab = 0.f, aa = 0.f, bb = 0.f, sa = 0.f, sb = 0.f;
    for (int i = threadIdx.x; i < TILE_ELEMS / 4; i += 256) {
        float4 a = A[i], b = B[i];
        ab += a.x * b.x + a.y * b.y + a.z * b.z + a.w * b.w;
        aa += a.x * a.x + a.y * a.y + a.z * a.z + a.w * a.w;
        bb += b.x * b.x + b.y * b.y + b.z * b.z + b.w * b.w;
        sa += a.x + a.y + a.z + a.w;
        sb += b.x + b.y + b.z + b.w;
    }
    __shared__ double s0[256], s1[256], s2[256], s3[256], s4[256];
    s0[threadIdx.x] = ab; s1[threadIdx.x] = aa; s2[threadIdx.x] = bb;
    s3[threadIdx.x] = sa; s4[threadIdx.x] = sb;
    __syncthreads();
    for (int o = 128; o > 0; o >>= 1) {
        if (threadIdx.x < o) {
            s0[threadIdx.x] += s0[threadIdx.x + o];
            s1[threadIdx.x] += s1[threadIdx.x + o];
            s2[threadIdx.x] += s2[threadIdx.x + o];
            s3[threadIdx.x] += s3[threadIdx.x + o];
            s4[threadIdx.x] += s4[threadIdx.x + o];
        }
        __syncthreads();
    }
    if (threadIdx.x == 0) {
        double w = (bi == bj) ? 1.0 : 2.0;
        atomicAdd(&g_prod[0], w * s0[0]);
        atomicAdd(&g_prod[1], w * s1[0]);
        atomicAdd(&g_prod[2], w * s2[0]);
        atomicAdd(&g_grand[0], w * s3[0]);
        atomicAdd(&g_grand[1], w * s4[0]);
    }
}

// ------------------------------- final ---------------------------------------
__global__ void k_final(const float* __restrict__ intra_wsi,
                        const float* __restrict__ intra_ct,
                        float* __restrict__ out) {
    __shared__ double s0[256], s1[256], s2[256];
    double mab = 0.0, maa = 0.0, mbb = 0.0;
    for (int i = threadIdx.x; i < BN; i += 256) {
        double ra = g_rowsum_a[i], rb = g_rowsum_b[i];
        mab += ra * rb; maa += ra * ra; mbb += rb * rb;
    }
    s0[threadIdx.x] = mab; s1[threadIdx.x] = maa; s2[threadIdx.x] = mbb;
    __syncthreads();
    for (int o = 128; o > 0; o >>= 1) {
        if (threadIdx.x < o) {
            s0[threadIdx.x] += s0[threadIdx.x + o];
            s1[threadIdx.x] += s1[threadIdx.x + o];
            s2[threadIdx.x] += s2[threadIdx.x + o];
        }
        __syncthreads();
    }
    if (threadIdx.x == 0) {
        double n = (double)BN, n2 = n * n;
        double Ga = g_grand[0], Gb = g_grand[1];
        double SAB = g_prod[0] - (2.0 / n) * s0[0] + Ga * Gb / n2;
        double SAA = g_prod[1] - (2.0 / n) * s1[0] + Ga * Ga / n2;
        double SBB = g_prod[2] - (2.0 / n) * s2[0] + Gb * Gb / n2;
        double dcov = SAB / n2, va = SAA / n2, vb = SBB / n2;
        double l_cca = 1.0 - dcov / sqrt(fmax(va * vb, 1e-8));
        double l_intra = (double)intra_wsi[0] + (double)intra_ct[0];
        out[0] = (float)(g_cox[0] + g_cox[1] + 0.1 * l_cca + 0.05 * l_intra);
    }
}

// ------------------------------- launch --------------------------------------
extern "C" void kernel_launch(void* const* d_in, const int* in_sizes, int n_in,
                              void* d_out, int out_size) {
    const float* risk_os   = (const float*)d_in[0];
    const float* risk_rfs  = (const float*)d_in[1];
    const float* z_ct      = (const float*)d_in[2];
    const float* z_wsi     = (const float*)d_in[3];
    const float* intra_wsi = (const float*)d_in[4];
    const float* intra_ct  = (const float*)d_in[5];
    const int* evt_os  = (const int*)d_in[6];
    const int* tm_os   = (const int*)d_in[7];
    const int* evt_rfs = (const int*)d_in[8];
    const int* tm_rfs  = (const int*)d_in[9];
    float* out = (float*)d_out;

    cudaFuncSetAttribute(k_gram, cudaFuncAttributeMaxDynamicSharedMemorySize, SMEM_TOTAL);

    k_zero<<<32, 256>>>();
    k_max<<<2, 256>>>(risk_os, risk_rfs);
    k_bucket<<<dim3(32, 2), 256>>>(risk_os, evt_os, tm_os, risk_rfs, evt_rfs, tm_rfs);
    k_cox<<<1, 32>>>();
    k_xx<<<BN / 8, 256>>>(z_ct, z_wsi);
    k_gram<<<dim3(64, 64, 2), 256, SMEM_TOTAL>>>(z_ct, z_wsi);
    k_prod<<<dim3(64, 64), 256>>>();
    k_final<<<1, 256>>>(intra_wsi, intra_ct, out);
}